// round 2
// baseline (speedup 1.0000x reference)
#include <cuda_runtime.h>
#include <cuda_bf16.h>
#include <cstdint>

#define Bn 1024
#define Sn 128
#define Dn 768
#define Cn 56
#define CPn 64
#define KC 64

// Packed bf16 weight matrix W[c][d], c in [0,64), cols 56..63 zero.
__device__ __nv_bfloat16 g_Wb[CPn * Dn];

__global__ void build_w_kernel(const float* __restrict__ w2, const float* __restrict__ w3,
                               const float* __restrict__ w4, const float* __restrict__ w5) {
    int i = blockIdx.x * blockDim.x + threadIdx.x;
    if (i >= CPn * Dn) return;
    int c = i / Dn, d = i % Dn;
    float v = 0.0f;
    if (c < 8)       { int f = c / 2;        int j = c % 2;        v = w2[(f * Dn + d) * 2 + j]; }
    else if (c < 20) { int cc = c - 8;  int f = cc / 3; int j = cc % 3; v = w3[(f * Dn + d) * 3 + j]; }
    else if (c < 36) { int cc = c - 20; int f = cc / 4; int j = cc % 4; v = w4[(f * Dn + d) * 4 + j]; }
    else if (c < 56) { int cc = c - 36; int f = cc / 5; int j = cc % 5; v = w5[(f * Dn + d) * 5 + j]; }
    g_Wb[c * Dn + d] = __float2bfloat16(v);
}

__device__ __forceinline__ uint32_t f2bf2(float2 v) {
    __nv_bfloat162 h = __float22bfloat162_rn(v);
    return *reinterpret_cast<uint32_t*>(&h);
}

// One CTA per batch row: GEMM (128 tok x 56 proj) + compaction + conv-maxpool + FC + sigmoid.
__global__ __launch_bounds__(256) void fused_kernel(
    const int* __restrict__ x, const float* __restrict__ hidden,
    const float* __restrict__ b2, const float* __restrict__ b3,
    const float* __restrict__ b4, const float* __restrict__ b5,
    const float* __restrict__ fcw, const float* __restrict__ fcb,
    float* __restrict__ out)
{
    __shared__ __align__(16) __nv_bfloat16 Bs[CPn][KC + 8];   // 9216 B, padded stride 72
    __shared__ float Psm[Sn][Cn + 1];                          // 128 x 57 f32, 29184 B
    __shared__ int order[Sn];
    __shared__ unsigned mask4[4];
    __shared__ int sh_len;
    __shared__ float feats[16];

    const int b    = blockIdx.x;
    const int tid  = threadIdx.x;
    const int warp = tid >> 5;
    const int lane = tid & 31;
    const int g    = lane >> 2;   // 0..7
    const int t4   = lane & 3;    // 0..3

    // ---- stable compaction order: non-pad positions first (ballot prefix) ----
    if (tid < Sn) {
        int nz = (x[b * Sn + tid] != 0);
        unsigned m = __ballot_sync(0xFFFFFFFFu, nz);
        if (lane == 0) mask4[warp] = m;
    }
    __syncthreads();
    if (tid < Sn) {
        unsigned mw = mask4[warp];
        int nzbefore = __popc(mw & ((1u << lane) - 1u));
        int nztot_before = 0;
        #pragma unroll
        for (int w = 0; w < 4; w++) if (w < warp) nztot_before += __popc(mask4[w]);
        int total = 0;
        #pragma unroll
        for (int w = 0; w < 4; w++) total += __popc(mask4[w]);
        int isnz = (mw >> lane) & 1;
        int pos = isnz ? (nztot_before + nzbefore)
                       : (total + (tid - nztot_before - nzbefore));
        order[pos] = tid;
        if (tid == 0) sh_len = total;
    }
    // (visibility to all threads guaranteed by syncthreads inside the GEMM loop)

    // ---- GEMM: Psm[128 x 56] = hidden_b[128 x 768] @ W^T (bf16 mma, f32 accum) ----
    const int rowA = warp * 16 + g;                       // this lane's first A row (and +8)
    const float* hrow0 = hidden + ((long)b * Sn + rowA) * Dn;
    const float* hrow1 = hrow0 + 8L * Dn;

    float acc[8][4];
    #pragma unroll
    for (int j = 0; j < 8; j++)
        #pragma unroll
        for (int q = 0; q < 4; q++) acc[j][q] = 0.0f;

    for (int k0 = 0; k0 < Dn; k0 += KC) {
        // load B stage: 64 rows x 64 bf16
        #pragma unroll
        for (int p = 0; p < 2; p++) {
            int u = tid + p * 256;      // 0..511
            int c = u >> 3, q = u & 7;
            *(uint4*)(&Bs[c][q * 8]) = *(const uint4*)(g_Wb + c * Dn + k0 + q * 8);
        }
        __syncthreads();
        #pragma unroll
        for (int ks = 0; ks < KC; ks += 16) {
            const int kk = k0 + ks + 2 * t4;
            // A fragments straight from global (each element read exactly once), cvt to bf16
            float2 f0 = *(const float2*)(hrow0 + kk);
            float2 f1 = *(const float2*)(hrow1 + kk);
            float2 f2 = *(const float2*)(hrow0 + kk + 8);
            float2 f3 = *(const float2*)(hrow1 + kk + 8);
            uint32_t a0 = f2bf2(f0), a1 = f2bf2(f1), a2 = f2bf2(f2), a3 = f2bf2(f3);
            #pragma unroll
            for (int j = 0; j < 8; j++) {
                uint32_t bb0 = *(const uint32_t*)(&Bs[8 * j + g][ks + 2 * t4]);
                uint32_t bb1 = *(const uint32_t*)(&Bs[8 * j + g][ks + 2 * t4 + 8]);
                asm volatile(
                    "mma.sync.aligned.m16n8k16.row.col.f32.bf16.bf16.f32 "
                    "{%0,%1,%2,%3}, {%4,%5,%6,%7}, {%8,%9}, {%0,%1,%2,%3};\n"
                    : "+f"(acc[j][0]), "+f"(acc[j][1]), "+f"(acc[j][2]), "+f"(acc[j][3])
                    : "r"(a0), "r"(a1), "r"(a2), "r"(a3), "r"(bb0), "r"(bb1));
            }
        }
        __syncthreads();
    }

    // spill accumulators to smem (cols 56..63 are padding -> skip j=7)
    #pragma unroll
    for (int j = 0; j < 7; j++) {
        int c = j * 8 + 2 * t4;
        Psm[rowA][c]         = acc[j][0];
        Psm[rowA][c + 1]     = acc[j][1];
        Psm[rowA + 8][c]     = acc[j][2];
        Psm[rowA + 8][c + 1] = acc[j][3];
    }
    __syncthreads();

    // ---- ragged conv + max-pool: 16 features, 2 per warp ----
    const int L = sh_len;
    #pragma unroll
    for (int r = 0; r < 2; r++) {
        int fi = warp + r * 8;               // 0..15 ; feats order = [k2 f0..3][k3][k4][k5]
        int kk = fi / 4 + 2;                 // kernel width 2..5
        int f  = fi % 4;
        int cb = (kk == 2 ? 0 : (kk == 3 ? 8 : (kk == 4 ? 20 : 36))) + f * kk;
        const float* bptr = (kk == 2 ? b2 : (kk == 3 ? b3 : (kk == 4 ? b4 : b5)));
        float bias = bptr[f];
        int nt = L - kk + 1;
        float m = -1e30f;
        for (int tp = lane; tp < nt; tp += 32) {
            float sconv = bias;
            for (int j = 0; j < kk; j++)
                sconv += Psm[order[tp + j]][cb + j];
            m = fmaxf(m, sconv);
        }
        #pragma unroll
        for (int off = 16; off; off >>= 1)
            m = fmaxf(m, __shfl_xor_sync(0xFFFFFFFFu, m, off));
        if (lane == 0) feats[fi] = m;
    }
    __syncthreads();

    if (tid == 0) {
        float z = fcb[0];
        #pragma unroll
        for (int i = 0; i < 16; i++) z += feats[i] * fcw[i];
        out[b] = 1.0f / (1.0f + expf(-z));
    }
}

extern "C" void kernel_launch(void* const* d_in, const int* in_sizes, int n_in,
                              void* d_out, int out_size) {
    const int*   x      = (const int*)d_in[0];
    const float* hidden = (const float*)d_in[1];
    const float* w2     = (const float*)d_in[2];
    const float* b2     = (const float*)d_in[3];
    const float* w3     = (const float*)d_in[4];
    const float* b3     = (const float*)d_in[5];
    const float* w4     = (const float*)d_in[6];
    const float* b4     = (const float*)d_in[7];
    const float* w5     = (const float*)d_in[8];
    const float* b5     = (const float*)d_in[9];
    const float* fcw    = (const float*)d_in[10];
    const float* fcb    = (const float*)d_in[11];
    float* out = (float*)d_out;

    build_w_kernel<<<(CPn * Dn + 255) / 256, 256>>>(w2, w3, w4, w5);
    fused_kernel<<<Bn, 256>>>(x, hidden, b2, b3, b4, b5, fcw, fcb, out);
}

// round 3
// speedup vs baseline: 1.0224x; 1.0224x over previous
#include <cuda_runtime.h>
#include <cuda_bf16.h>
#include <cstdint>

#define Bn 1024
#define Sn 128
#define Dn 768
#define Cn 56
#define KC 64
#define NCHUNK 12

// Packed bf16 weight matrix W[c][d_logical], c in [0,56).
// k-columns are PERMUTED within each 16-block so that a lane's float4 A-load
// at phys col 4*t4 directly yields the mma fragment's logical k pairs.
__device__ __nv_bfloat16 g_Wb[Cn * Dn];

__global__ void build_w_kernel(const float* __restrict__ w2, const float* __restrict__ w3,
                               const float* __restrict__ w4, const float* __restrict__ w5) {
    int i = blockIdx.x * blockDim.x + threadIdx.x;
    if (i >= Cn * Dn) return;
    int c = i / Dn, d = i % Dn;          // d = logical k index
    // logical -> physical within the 16-block: l<8: p=4*(l>>1)+(l&1); else p=4*((l-8)>>1)+2+(l&1)
    int blk = d >> 4, l = d & 15;
    int p = (l < 8) ? (((l >> 1) << 2) + (l & 1))
                    : ((((l - 8) >> 1) << 2) + 2 + (l & 1));
    int dp = (blk << 4) + p;             // physical k column in original weights
    float v;
    if (c < 8)       { int f = c / 2;        int j = c % 2;        v = w2[(f * Dn + dp) * 2 + j]; }
    else if (c < 20) { int cc = c - 8;  int f = cc / 3; int j = cc % 3; v = w3[(f * Dn + dp) * 3 + j]; }
    else if (c < 36) { int cc = c - 20; int f = cc / 4; int j = cc % 4; v = w4[(f * Dn + dp) * 4 + j]; }
    else             { int cc = c - 36; int f = cc / 5; int j = cc % 5; v = w5[(f * Dn + dp) * 5 + j]; }
    g_Wb[c * Dn + d] = __float2bfloat16(v);
}

__device__ __forceinline__ uint32_t f2bf2(float lo, float hi) {
    __nv_bfloat162 h = __float22bfloat162_rn(make_float2(lo, hi));
    return *reinterpret_cast<uint32_t*>(&h);
}

__device__ __forceinline__ void cp16(uint32_t dst_smem, const void* src) {
    asm volatile("cp.async.cg.shared.global [%0], [%1], 16;\n" :: "r"(dst_smem), "l"(src));
}

// One CTA per batch row: GEMM (128 tok x 56 proj, bf16 HMMA) + compaction +
// ragged conv/max-pool + FC + sigmoid, fully fused.
__global__ __launch_bounds__(256) void fused_kernel(
    const int* __restrict__ x, const float* __restrict__ hidden,
    const float* __restrict__ b2, const float* __restrict__ b3,
    const float* __restrict__ b4, const float* __restrict__ b5,
    const float* __restrict__ fcw, const float* __restrict__ fcb,
    float* __restrict__ out)
{
    __shared__ __align__(16) __nv_bfloat16 Bs[2][Cn][KC + 8];  // 2 x 56 x 72 bf16 = 16128 B
    __shared__ float Psm[Sn][Cn + 1];                           // 128 x 57 f32
    __shared__ int order[Sn];
    __shared__ unsigned mask4[4];
    __shared__ int sh_len;
    __shared__ float feats[16];

    const int b    = blockIdx.x;
    const int tid  = threadIdx.x;
    const int warp = tid >> 5;
    const int lane = tid & 31;
    const int g    = lane >> 2;   // 0..7
    const int t4   = lane & 3;    // 0..3

    const uint32_t bs_base = (uint32_t)__cvta_generic_to_shared(&Bs[0][0][0]);

    // ---- stable compaction order (ballot prefix) ----
    if (tid < Sn) {
        int nz = (x[b * Sn + tid] != 0);
        unsigned m = __ballot_sync(0xFFFFFFFFu, nz);
        if (lane == 0) mask4[warp] = m;
    }
    __syncthreads();
    if (tid < Sn) {
        unsigned mw = mask4[warp];
        int nzbefore = __popc(mw & ((1u << lane) - 1u));
        int nztot_before = 0, total = 0;
        #pragma unroll
        for (int w = 0; w < 4; w++) { if (w < warp) nztot_before += __popc(mask4[w]); total += __popc(mask4[w]); }
        int isnz = (mw >> lane) & 1;
        int pos = isnz ? (nztot_before + nzbefore)
                       : (total + (tid - nztot_before - nzbefore));
        order[pos] = tid;
        if (tid == 0) sh_len = total;
    }

    // ---- B staging helper: chunk ci -> buffer buf via cp.async ----
    auto issueB = [&](int ci, int buf) {
        #pragma unroll
        for (int u = tid; u < Cn * 8; u += 256) {       // 448 16B pieces
            int c = u >> 3, q = u & 7;
            cp16(bs_base + (uint32_t)(buf * Cn * (KC + 8) + c * (KC + 8) + q * 8) * 2,
                 g_Wb + c * Dn + ci * KC + q * 8);
        }
        asm volatile("cp.async.commit_group;\n");
    };

    issueB(0, 0);
    issueB(1, 1);

    // ---- GEMM mainloop ----
    const int rowA = warp * 16 + g;
    const float* hbase0 = hidden + ((long)b * Sn + rowA) * Dn;
    const float* hbase1 = hbase0 + 8L * Dn;

    float acc[7][4];
    #pragma unroll
    for (int j = 0; j < 7; j++)
        #pragma unroll
        for (int q = 0; q < 4; q++) acc[j][q] = 0.0f;

    #pragma unroll 1
    for (int ci = 0; ci < NCHUNK; ci++) {
        // prefetch A fragments for this chunk (independent LDG.128s, issued
        // before the barrier wait so latency overlaps the B pipeline)
        const float* h0 = hbase0 + ci * KC + 4 * t4;
        const float* h1 = hbase1 + ci * KC + 4 * t4;
        uint32_t Ar[4][4];
        #pragma unroll
        for (int s = 0; s < 4; s++) {
            float4 f0 = *(const float4*)(h0 + 16 * s);
            float4 f1 = *(const float4*)(h1 + 16 * s);
            Ar[s][0] = f2bf2(f0.x, f0.y);
            Ar[s][2] = f2bf2(f0.z, f0.w);
            Ar[s][1] = f2bf2(f1.x, f1.y);
            Ar[s][3] = f2bf2(f1.z, f1.w);
        }

        if (ci < NCHUNK - 1) asm volatile("cp.async.wait_group 1;\n" ::: "memory");
        else                 asm volatile("cp.async.wait_group 0;\n" ::: "memory");
        __syncthreads();

        const int bi = ci & 1;
        #pragma unroll
        for (int s = 0; s < 4; s++) {
            #pragma unroll
            for (int j = 0; j < 7; j++) {
                uint32_t bb0 = *(const uint32_t*)(&Bs[bi][8 * j + g][16 * s + 2 * t4]);
                uint32_t bb1 = *(const uint32_t*)(&Bs[bi][8 * j + g][16 * s + 2 * t4 + 8]);
                asm volatile(
                    "mma.sync.aligned.m16n8k16.row.col.f32.bf16.bf16.f32 "
                    "{%0,%1,%2,%3}, {%4,%5,%6,%7}, {%8,%9}, {%0,%1,%2,%3};\n"
                    : "+f"(acc[j][0]), "+f"(acc[j][1]), "+f"(acc[j][2]), "+f"(acc[j][3])
                    : "r"(Ar[s][0]), "r"(Ar[s][1]), "r"(Ar[s][2]), "r"(Ar[s][3]),
                      "r"(bb0), "r"(bb1));
            }
        }
        __syncthreads();

        if (ci + 2 < NCHUNK) issueB(ci + 2, bi);
    }

    // ---- spill P to smem ----
    #pragma unroll
    for (int j = 0; j < 7; j++) {
        int c = j * 8 + 2 * t4;
        Psm[rowA][c]         = acc[j][0];
        Psm[rowA][c + 1]     = acc[j][1];
        Psm[rowA + 8][c]     = acc[j][2];
        Psm[rowA + 8][c + 1] = acc[j][3];
    }
    __syncthreads();

    // ---- ragged conv + max-pool: 16 features, 2 per warp ----
    const int L = sh_len;
    #pragma unroll
    for (int r = 0; r < 2; r++) {
        int fi = warp + r * 8;
        int kk = fi / 4 + 2;
        int f  = fi % 4;
        int cb = (kk == 2 ? 0 : (kk == 3 ? 8 : (kk == 4 ? 20 : 36))) + f * kk;
        const float* bptr = (kk == 2 ? b2 : (kk == 3 ? b3 : (kk == 4 ? b4 : b5)));
        float bias = bptr[f];
        int nt = L - kk + 1;
        float m = -1e30f;
        for (int tp = lane; tp < nt; tp += 32) {
            float sconv = bias;
            for (int j = 0; j < kk; j++)
                sconv += Psm[order[tp + j]][cb + j];
            m = fmaxf(m, sconv);
        }
        #pragma unroll
        for (int off = 16; off; off >>= 1)
            m = fmaxf(m, __shfl_xor_sync(0xFFFFFFFFu, m, off));
        if (lane == 0) feats[fi] = m;
    }
    __syncthreads();

    if (tid == 0) {
        float z = fcb[0];
        #pragma unroll
        for (int i = 0; i < 16; i++) z += feats[i] * fcw[i];
        out[b] = 1.0f / (1.0f + expf(-z));
    }
}

extern "C" void kernel_launch(void* const* d_in, const int* in_sizes, int n_in,
                              void* d_out, int out_size) {
    const int*   x      = (const int*)d_in[0];
    const float* hidden = (const float*)d_in[1];
    const float* w2     = (const float*)d_in[2];
    const float* b2     = (const float*)d_in[3];
    const float* w3     = (const float*)d_in[4];
    const float* b3     = (const float*)d_in[5];
    const float* w4     = (const float*)d_in[6];
    const float* b4     = (const float*)d_in[7];
    const float* w5     = (const float*)d_in[8];
    const float* b5     = (const float*)d_in[9];
    const float* fcw    = (const float*)d_in[10];
    const float* fcb    = (const float*)d_in[11];
    float* out = (float*)d_out;

    build_w_kernel<<<(Cn * Dn + 255) / 256, 256>>>(w2, w3, w4, w5);
    fused_kernel<<<Bn, 256>>>(x, hidden, b2, b3, b4, b5, fcw, fcb, out);
}

// round 4
// speedup vs baseline: 1.1854x; 1.1594x over previous
#include <cuda_runtime.h>
#include <cuda_bf16.h>
#include <cstdint>

#define Bn 1024
#define Sn 128
#define Dn 768
#define Cn 56
#define KC 64
#define NCHUNK 12
#define NBUF 3
#define BSTRIDE (KC + 8)

// Packed bf16 weight matrix W[c][d_logical], c in [0,56).
// k-columns PERMUTED within each 16-block so a lane's float4 A-load at
// phys col 4*t4 directly yields the mma fragment's logical k pairs.
__device__ __nv_bfloat16 g_Wb[Cn * Dn];

__global__ void build_w_kernel(const float* __restrict__ w2, const float* __restrict__ w3,
                               const float* __restrict__ w4, const float* __restrict__ w5) {
    int i = blockIdx.x * blockDim.x + threadIdx.x;
    if (i >= Cn * Dn) return;
    int c = i / Dn, d = i % Dn;          // d = logical k index
    int blk = d >> 4, l = d & 15;
    int p = (l < 8) ? (((l >> 1) << 2) + (l & 1))
                    : ((((l - 8) >> 1) << 2) + 2 + (l & 1));
    int dp = (blk << 4) + p;             // physical k column in original weights
    float v;
    if (c < 8)       { int f = c / 2;        int j = c % 2;        v = w2[(f * Dn + dp) * 2 + j]; }
    else if (c < 20) { int cc = c - 8;  int f = cc / 3; int j = cc % 3; v = w3[(f * Dn + dp) * 3 + j]; }
    else if (c < 36) { int cc = c - 20; int f = cc / 4; int j = cc % 4; v = w4[(f * Dn + dp) * 4 + j]; }
    else             { int cc = c - 36; int f = cc / 5; int j = cc % 5; v = w5[(f * Dn + dp) * 5 + j]; }
    g_Wb[c * Dn + d] = __float2bfloat16(v);
}

__device__ __forceinline__ uint32_t f2bf2(float lo, float hi) {
    __nv_bfloat162 h = __float22bfloat162_rn(make_float2(lo, hi));
    return *reinterpret_cast<uint32_t*>(&h);
}

__device__ __forceinline__ void cp16(uint32_t dst_smem, const void* src) {
    asm volatile("cp.async.cg.shared.global [%0], [%1], 16;\n" :: "r"(dst_smem), "l"(src));
}

#define SMEM_BYTES ((Sn * (Cn + 1) * 4) > (NBUF * Cn * BSTRIDE * 2) ? (Sn * (Cn + 1) * 4) : (NBUF * Cn * BSTRIDE * 2))

__global__ __launch_bounds__(256, 4) void fused_kernel(
    const int* __restrict__ x, const float* __restrict__ hidden,
    const float* __restrict__ b2, const float* __restrict__ b3,
    const float* __restrict__ b4, const float* __restrict__ b5,
    const float* __restrict__ fcw, const float* __restrict__ fcb,
    float* __restrict__ out)
{
    // Bs (mainloop) and Psm (epilogue) share the same storage.
    __shared__ __align__(16) unsigned char sraw[SMEM_BYTES];
    __nv_bfloat16* Bsf = reinterpret_cast<__nv_bfloat16*>(sraw);   // [NBUF][Cn][BSTRIDE]
    float (*Psm)[Cn + 1] = reinterpret_cast<float (*)[Cn + 1]>(sraw);

    __shared__ int order[Sn];
    __shared__ unsigned mask4[4];
    __shared__ int sh_len;
    __shared__ float feats[16];

    const int b    = blockIdx.x;
    const int tid  = threadIdx.x;
    const int warp = tid >> 5;
    const int lane = tid & 31;
    const int g    = lane >> 2;   // 0..7
    const int t4   = lane & 3;    // 0..3

    const uint32_t bs_base = (uint32_t)__cvta_generic_to_shared(Bsf);

    // ---- stable compaction order (ballot prefix) ----
    if (tid < Sn) {
        int nz = (x[b * Sn + tid] != 0);
        unsigned m = __ballot_sync(0xFFFFFFFFu, nz);
        if (lane == 0) mask4[warp] = m;
    }
    __syncthreads();
    if (tid < Sn) {
        unsigned mw = mask4[warp];
        int nzbefore = __popc(mw & ((1u << lane) - 1u));
        int nztot_before = 0, total = 0;
        #pragma unroll
        for (int w = 0; w < 4; w++) { if (w < warp) nztot_before += __popc(mask4[w]); total += __popc(mask4[w]); }
        int isnz = (mw >> lane) & 1;
        int pos = isnz ? (nztot_before + nzbefore)
                       : (total + (tid - nztot_before - nzbefore));
        order[pos] = tid;
        if (tid == 0) sh_len = total;
    }

    // ---- B staging: chunk ci -> buffer buf ----
    auto issueB = [&](int ci, int buf) {
        #pragma unroll
        for (int u = tid; u < Cn * 8; u += 256) {       // 448 16B pieces
            int c = u >> 3, q = u & 7;
            cp16(bs_base + (uint32_t)(buf * Cn * BSTRIDE + c * BSTRIDE + q * 8) * 2,
                 g_Wb + c * Dn + ci * KC + q * 8);
        }
        asm volatile("cp.async.commit_group;\n");
    };

    issueB(0, 0);
    issueB(1, 1);

    // ---- GEMM mainloop: acc[7][4] = P tile ----
    const int rowA = warp * 16 + g;
    const float* hbase0 = hidden + ((long)b * Sn + rowA) * Dn + 4 * t4;
    const float* hbase1 = hbase0 + 8L * Dn;

    float acc[7][4];
    #pragma unroll
    for (int j = 0; j < 7; j++)
        #pragma unroll
        for (int q = 0; q < 4; q++) acc[j][q] = 0.0f;

    #pragma unroll 1
    for (int ci = 0; ci < NCHUNK; ci++) {
        const float* h0 = hbase0 + ci * KC;
        const float* h1 = hbase1 + ci * KC;

        // phase-0 A fragments (s=0,1) before the wait: overlap with barrier
        uint32_t Ar[2][4];
        #pragma unroll
        for (int s = 0; s < 2; s++) {
            float4 f0 = *(const float4*)(h0 + 16 * s);
            float4 f1 = *(const float4*)(h1 + 16 * s);
            Ar[s][0] = f2bf2(f0.x, f0.y);
            Ar[s][2] = f2bf2(f0.z, f0.w);
            Ar[s][1] = f2bf2(f1.x, f1.y);
            Ar[s][3] = f2bf2(f1.z, f1.w);
        }

        if (ci < NCHUNK - 1) asm volatile("cp.async.wait_group 1;\n" ::: "memory");
        else                 asm volatile("cp.async.wait_group 0;\n" ::: "memory");
        __syncthreads();   // single barrier per chunk

        if (ci + 2 < NCHUNK) issueB(ci + 2, (ci + 2) % NBUF);

        const __nv_bfloat16* Bbuf = Bsf + (ci % NBUF) * Cn * BSTRIDE;

        #pragma unroll
        for (int half = 0; half < 2; half++) {
            // prefetch next half's A before computing this half
            uint32_t Anx[2][4];
            if (half == 0) {
                #pragma unroll
                for (int s = 0; s < 2; s++) {
                    float4 f0 = *(const float4*)(h0 + 16 * (s + 2));
                    float4 f1 = *(const float4*)(h1 + 16 * (s + 2));
                    Anx[s][0] = f2bf2(f0.x, f0.y);
                    Anx[s][2] = f2bf2(f0.z, f0.w);
                    Anx[s][1] = f2bf2(f1.x, f1.y);
                    Anx[s][3] = f2bf2(f1.z, f1.w);
                }
            }
            #pragma unroll
            for (int s = 0; s < 2; s++) {
                const int so = half * 2 + s;
                #pragma unroll
                for (int j = 0; j < 7; j++) {
                    const __nv_bfloat16* brow = Bbuf + (8 * j + g) * BSTRIDE + 16 * so + 2 * t4;
                    uint32_t bb0 = *(const uint32_t*)(brow);
                    uint32_t bb1 = *(const uint32_t*)(brow + 8);
                    asm volatile(
                        "mma.sync.aligned.m16n8k16.row.col.f32.bf16.bf16.f32 "
                        "{%0,%1,%2,%3}, {%4,%5,%6,%7}, {%8,%9}, {%0,%1,%2,%3};\n"
                        : "+f"(acc[j][0]), "+f"(acc[j][1]), "+f"(acc[j][2]), "+f"(acc[j][3])
                        : "r"(Ar[s][0]), "r"(Ar[s][1]), "r"(Ar[s][2]), "r"(Ar[s][3]),
                          "r"(bb0), "r"(bb1));
                }
            }
            if (half == 0) {
                #pragma unroll
                for (int s = 0; s < 2; s++)
                    #pragma unroll
                    for (int q = 0; q < 4; q++) Ar[s][q] = Anx[s][q];
            }
        }
    }

    // ---- all warps done reading Bs before Psm overwrites it ----
    __syncthreads();
    #pragma unroll
    for (int j = 0; j < 7; j++) {
        int c = j * 8 + 2 * t4;
        Psm[rowA][c]         = acc[j][0];
        Psm[rowA][c + 1]     = acc[j][1];
        Psm[rowA + 8][c]     = acc[j][2];
        Psm[rowA + 8][c + 1] = acc[j][3];
    }
    __syncthreads();

    // ---- ragged conv + max-pool: 16 features, 2 per warp ----
    const int L = sh_len;
    #pragma unroll
    for (int r = 0; r < 2; r++) {
        int fi = warp + r * 8;
        int kk = fi / 4 + 2;
        int f  = fi % 4;
        int cb = (kk == 2 ? 0 : (kk == 3 ? 8 : (kk == 4 ? 20 : 36))) + f * kk;
        const float* bptr = (kk == 2 ? b2 : (kk == 3 ? b3 : (kk == 4 ? b4 : b5)));
        float bias = bptr[f];
        int nt = L - kk + 1;
        float m = -1e30f;
        for (int tp = lane; tp < nt; tp += 32) {
            float sconv = bias;
            for (int j = 0; j < kk; j++)
                sconv += Psm[order[tp + j]][cb + j];
            m = fmaxf(m, sconv);
        }
        #pragma unroll
        for (int off = 16; off; off >>= 1)
            m = fmaxf(m, __shfl_xor_sync(0xFFFFFFFFu, m, off));
        if (lane == 0) feats[fi] = m;
    }
    __syncthreads();

    if (tid == 0) {
        float z = fcb[0];
        #pragma unroll
        for (int i = 0; i < 16; i++) z += feats[i] * fcw[i];
        out[b] = 1.0f / (1.0f + expf(-z));
    }
}

extern "C" void kernel_launch(void* const* d_in, const int* in_sizes, int n_in,
                              void* d_out, int out_size) {
    const int*   x      = (const int*)d_in[0];
    const float* hidden = (const float*)d_in[1];
    const float* w2     = (const float*)d_in[2];
    const float* b2     = (const float*)d_in[3];
    const float* w3     = (const float*)d_in[4];
    const float* b3     = (const float*)d_in[5];
    const float* w4     = (const float*)d_in[6];
    const float* b4     = (const float*)d_in[7];
    const float* w5     = (const float*)d_in[8];
    const float* b5     = (const float*)d_in[9];
    const float* fcw    = (const float*)d_in[10];
    const float* fcb    = (const float*)d_in[11];
    float* out = (float*)d_out;

    build_w_kernel<<<(Cn * Dn + 255) / 256, 256>>>(w2, w3, w4, w5);
    fused_kernel<<<Bn, 256>>>(x, hidden, b2, b3, b4, b5, fcw, fcb, out);
}

// round 5
// speedup vs baseline: 1.2391x; 1.0453x over previous
#include <cuda_runtime.h>
#include <cuda_bf16.h>
#include <cstdint>

#define Bn 1024
#define Sn 128
#define Dn 768
#define Cn 56
#define KC 32
#define NCHUNK 24
#define NBUF 3
#define AST (Sn * KC)           /* floats per A stage = 4096 (16KB) */
#define BROW 40                 /* bf16 per B row (32 data + 8 pad) */
#define BST (Cn * BROW)         /* bf16 per B stage = 2240 */
#define A_BYTES (NBUF * AST * 4)      /* 49152 */
#define B_BYTES (NBUF * BST * 2)      /* 13440 */
#define SMEM_DYN (A_BYTES + B_BYTES)  /* 62592 */

// Packed bf16 weight matrix W[c][d_logical], c in [0,56).
// k-columns PERMUTED within each 16-block so a lane's float4 A-load at
// phys col 4*t4 (+16s) directly yields the mma fragment's logical k pairs.
__device__ __nv_bfloat16 g_Wb[Cn * Dn];

__global__ void build_w_kernel(const float* __restrict__ w2, const float* __restrict__ w3,
                               const float* __restrict__ w4, const float* __restrict__ w5) {
    int i = blockIdx.x * blockDim.x + threadIdx.x;
    if (i >= Cn * Dn) return;
    int c = i / Dn, d = i % Dn;          // d = logical k index
    int blk = d >> 4, l = d & 15;
    int p = (l < 8) ? (((l >> 1) << 2) + (l & 1))
                    : ((((l - 8) >> 1) << 2) + 2 + (l & 1));
    int dp = (blk << 4) + p;             // physical k column in original weights
    float v;
    if (c < 8)       { int f = c / 2;        int j = c % 2;        v = w2[(f * Dn + dp) * 2 + j]; }
    else if (c < 20) { int cc = c - 8;  int f = cc / 3; int j = cc % 3; v = w3[(f * Dn + dp) * 3 + j]; }
    else if (c < 36) { int cc = c - 20; int f = cc / 4; int j = cc % 4; v = w4[(f * Dn + dp) * 4 + j]; }
    else             { int cc = c - 36; int f = cc / 5; int j = cc % 5; v = w5[(f * Dn + dp) * 5 + j]; }
    g_Wb[c * Dn + d] = __float2bfloat16(v);
}

__device__ __forceinline__ uint32_t f2bf2(float lo, float hi) {
    __nv_bfloat162 h = __float22bfloat162_rn(make_float2(lo, hi));
    return *reinterpret_cast<uint32_t*>(&h);
}

__device__ __forceinline__ void cp16(uint32_t dst_smem, const void* src) {
    asm volatile("cp.async.cg.shared.global [%0], [%1], 16;\n" :: "r"(dst_smem), "l"(src));
}

__global__ __launch_bounds__(256, 3) void fused_kernel(
    const int* __restrict__ x, const float* __restrict__ hidden,
    const float* __restrict__ b2, const float* __restrict__ b3,
    const float* __restrict__ b4, const float* __restrict__ b5,
    const float* __restrict__ fcw, const float* __restrict__ fcb,
    float* __restrict__ out)
{
    extern __shared__ __align__(16) unsigned char sraw[];
    float* As = reinterpret_cast<float*>(sraw);                        // [NBUF][128][32], XOR-swizzled
    __nv_bfloat16* Bsm = reinterpret_cast<__nv_bfloat16*>(sraw + A_BYTES); // [NBUF][56][40]
    float (*Psm)[Cn + 1] = reinterpret_cast<float (*)[Cn + 1]>(sraw);  // epilogue reuse of A region

    __shared__ int order[Sn];
    __shared__ unsigned mask4[4];
    __shared__ int sh_len;
    __shared__ float feats[16];

    const int b    = blockIdx.x;
    const int tid  = threadIdx.x;
    const int warp = tid >> 5;
    const int lane = tid & 31;
    const int g    = lane >> 2;   // 0..7
    const int t4   = lane & 3;    // 0..3

    const uint32_t a_base = (uint32_t)__cvta_generic_to_shared(As);
    const uint32_t b_base = (uint32_t)__cvta_generic_to_shared(Bsm);
    const float* hidb = hidden + (long)b * Sn * Dn;

    // ---- async stage issue: A (swizzled) + B, one commit group per chunk ----
    auto issueAB = [&](int ci, int buf) {
        const float* hsrc = hidb + ci * KC;
        #pragma unroll
        for (int p = 0; p < 4; p++) {
            int u = tid + p * 256;          // 0..1023
            int r = u >> 3, q = u & 7;      // row, 16B-granule within row
            int rg = r & 7;
            int pm = ((rg & 1) << 2) | (rg >> 1);
            cp16(a_base + (uint32_t)(buf * AST + r * KC + 4 * (q ^ pm)) * 4,
                 hsrc + (long)r * Dn + q * 4);
        }
        if (tid < 224) {
            int c = tid >> 2, q = tid & 3;
            cp16(b_base + (uint32_t)(buf * BST + c * BROW + q * 8) * 2,
                 g_Wb + c * Dn + ci * KC + q * 8);
        }
        asm volatile("cp.async.commit_group;\n");
    };

    issueAB(0, 0);
    issueAB(1, 1);

    // ---- stable compaction order (overlaps with first loads) ----
    if (tid < Sn) {
        int nz = (x[b * Sn + tid] != 0);
        unsigned m = __ballot_sync(0xFFFFFFFFu, nz);
        if (lane == 0) mask4[warp] = m;
    }
    __syncthreads();
    if (tid < Sn) {
        unsigned mw = mask4[warp];
        int nzbefore = __popc(mw & ((1u << lane) - 1u));
        int nztot_before = 0, total = 0;
        #pragma unroll
        for (int w = 0; w < 4; w++) { if (w < warp) nztot_before += __popc(mask4[w]); total += __popc(mask4[w]); }
        int isnz = (mw >> lane) & 1;
        int pos = isnz ? (nztot_before + nzbefore)
                       : (total + (tid - nztot_before - nzbefore));
        order[pos] = tid;
        if (tid == 0) sh_len = total;
    }

    // ---- GEMM mainloop ----
    float acc[7][4];
    #pragma unroll
    for (int j = 0; j < 7; j++)
        #pragma unroll
        for (int q = 0; q < 4; q++) acc[j][q] = 0.0f;

    const int pm = ((g & 1) << 2) | (g >> 1);
    const int rowA = warp * 16 + g;

    #pragma unroll 1
    for (int ci = 0; ci < NCHUNK; ci++) {
        if (ci < NCHUNK - 1) asm volatile("cp.async.wait_group 1;\n" ::: "memory");
        else                 asm volatile("cp.async.wait_group 0;\n" ::: "memory");
        __syncthreads();   // single barrier per chunk

        if (ci + 2 < NCHUNK) issueAB(ci + 2, (ci + 2) % NBUF);

        const float* Abuf = As + (ci % NBUF) * AST;
        const __nv_bfloat16* Bbuf = Bsm + (ci % NBUF) * BST;

        #pragma unroll
        for (int s = 0; s < 2; s++) {
            int q0 = (t4 + 4 * s) ^ pm;
            float4 f0 = *(const float4*)(Abuf + rowA * KC + 4 * q0);
            float4 f1 = *(const float4*)(Abuf + (rowA + 8) * KC + 4 * q0);
            uint32_t a0 = f2bf2(f0.x, f0.y), a2 = f2bf2(f0.z, f0.w);
            uint32_t a1 = f2bf2(f1.x, f1.y), a3 = f2bf2(f1.z, f1.w);
            #pragma unroll
            for (int j = 0; j < 7; j++) {
                const __nv_bfloat16* brow = Bbuf + (8 * j + g) * BROW + 16 * s + 2 * t4;
                uint32_t bb0 = *(const uint32_t*)brow;
                uint32_t bb1 = *(const uint32_t*)(brow + 8);
                asm volatile(
                    "mma.sync.aligned.m16n8k16.row.col.f32.bf16.bf16.f32 "
                    "{%0,%1,%2,%3}, {%4,%5,%6,%7}, {%8,%9}, {%0,%1,%2,%3};\n"
                    : "+f"(acc[j][0]), "+f"(acc[j][1]), "+f"(acc[j][2]), "+f"(acc[j][3])
                    : "r"(a0), "r"(a1), "r"(a2), "r"(a3), "r"(bb0), "r"(bb1));
            }
        }
    }

    // ---- all warps done with As before Psm overwrites it ----
    __syncthreads();
    #pragma unroll
    for (int j = 0; j < 7; j++) {
        int c = j * 8 + 2 * t4;
        Psm[rowA][c]         = acc[j][0];
        Psm[rowA][c + 1]     = acc[j][1];
        Psm[rowA + 8][c]     = acc[j][2];
        Psm[rowA + 8][c + 1] = acc[j][3];
    }
    __syncthreads();

    // ---- ragged conv + max-pool: 16 features, 2 per warp ----
    const int L = sh_len;
    #pragma unroll
    for (int r = 0; r < 2; r++) {
        int fi = warp + r * 8;
        int kk = fi / 4 + 2;
        int f  = fi % 4;
        int cb = (kk == 2 ? 0 : (kk == 3 ? 8 : (kk == 4 ? 20 : 36))) + f * kk;
        const float* bptr = (kk == 2 ? b2 : (kk == 3 ? b3 : (kk == 4 ? b4 : b5)));
        float bias = bptr[f];
        int nt = L - kk + 1;
        float m = -1e30f;
        for (int tp = lane; tp < nt; tp += 32) {
            float sconv = bias;
            for (int j = 0; j < kk; j++)
                sconv += Psm[order[tp + j]][cb + j];
            m = fmaxf(m, sconv);
        }
        #pragma unroll
        for (int off = 16; off; off >>= 1)
            m = fmaxf(m, __shfl_xor_sync(0xFFFFFFFFu, m, off));
        if (lane == 0) feats[fi] = m;
    }
    __syncthreads();

    if (tid == 0) {
        float z = fcb[0];
        #pragma unroll
        for (int i = 0; i < 16; i++) z += feats[i] * fcw[i];
        out[b] = 1.0f / (1.0f + expf(-z));
    }
}

extern "C" void kernel_launch(void* const* d_in, const int* in_sizes, int n_in,
                              void* d_out, int out_size) {
    const int*   x      = (const int*)d_in[0];
    const float* hidden = (const float*)d_in[1];
    const float* w2     = (const float*)d_in[2];
    const float* b2     = (const float*)d_in[3];
    const float* w3     = (const float*)d_in[4];
    const float* b3     = (const float*)d_in[5];
    const float* w4     = (const float*)d_in[6];
    const float* b4     = (const float*)d_in[7];
    const float* w5     = (const float*)d_in[8];
    const float* b5     = (const float*)d_in[9];
    const float* fcw    = (const float*)d_in[10];
    const float* fcb    = (const float*)d_in[11];
    float* out = (float*)d_out;

    cudaFuncSetAttribute(fused_kernel, cudaFuncAttributeMaxDynamicSharedMemorySize, SMEM_DYN);

    build_w_kernel<<<(Cn * Dn + 255) / 256, 256>>>(w2, w3, w4, w5);
    fused_kernel<<<Bn, 256, SMEM_DYN>>>(x, hidden, b2, b3, b4, b5, fcw, fcb, out);
}